// round 6
// baseline (speedup 1.0000x reference)
#include <cuda_runtime.h>
#include <cuda_bf16.h>
#include <cstdint>

#define N_ATOMS 10000
#define N_PAIRS 250000
#define NPROP   128

// ---------------- device scratch (static, allocation-free) ----------------
__device__ int   g_counts[N_ATOMS];
__device__ int   g_cursor[N_ATOMS];
__device__ int   g_offsets[N_ATOMS + 1];
__device__ int   g_pairlist[N_PAIRS];
__device__ float g_pxacc[(size_t)N_ATOMS * 3 * NPROP];
__device__ int   g_next;

// ---------------- K0: zero counts / cursors / work queue ----------------
__global__ void k_init() {
    int t = blockIdx.x * blockDim.x + threadIdx.x;
    if (t < N_ATOMS) { g_counts[t] = 0; g_cursor[t] = 0; }
    if (t == 0) g_next = 0;
}

// ---------------- K1: histogram of ind_i ----------------
__global__ void k_hist(const int* __restrict__ ind2) {
    int p = blockIdx.x * blockDim.x + threadIdx.x;
    if (p < N_PAIRS) atomicAdd(&g_counts[ind2[2 * p]], 1);
}

// ---------------- K2: exclusive scan of counts -> offsets (1 block) -------
__global__ void k_scan() {
    __shared__ int part[1024];
    const int PER = 10;
    int t = threadIdx.x;
    int local[PER];
    int sum = 0;
#pragma unroll
    for (int r = 0; r < PER; r++) {
        int idx = t * PER + r;
        int v = (idx < N_ATOMS) ? g_counts[idx] : 0;
        local[r] = sum;
        sum += v;
    }
    part[t] = sum;
    __syncthreads();
    for (int off = 1; off < 1024; off <<= 1) {
        int v = (t >= off) ? part[t - off] : 0;
        __syncthreads();
        part[t] += v;
        __syncthreads();
    }
    int base = (t > 0) ? part[t - 1] : 0;
#pragma unroll
    for (int r = 0; r < PER; r++) {
        int idx = t * PER + r;
        if (idx < N_ATOMS) g_offsets[idx] = base + local[r];
    }
    if (t == 1023) g_offsets[N_ATOMS] = part[1023];
}

// ---------------- K3: scatter pair ids into CSR ----------------
__global__ void k_scatter(const int* __restrict__ ind2) {
    int p = blockIdx.x * blockDim.x + threadIdx.x;
    if (p < N_PAIRS) {
        int i = ind2[2 * p];
        int pos = atomicAdd(&g_cursor[i], 1);
        g_pairlist[g_offsets[i] + pos] = p;
    }
}

// ---------------- K3b: per-segment sort (warp odd-even in shared) ---------
__global__ void __launch_bounds__(128) k_sort() {
    __shared__ int buf[4][96];
    int wd = threadIdx.x >> 5, lane = threadIdx.x & 31;
    int a = blockIdx.x * 4 + wd;
    if (a >= N_ATOMS) return;
    int s = g_offsets[a], e = g_offsets[a + 1];
    int n = e - s;
    if (n <= 1) return;
    if (n <= 96) {
        for (int i = lane; i < n; i += 32) buf[wd][i] = g_pairlist[s + i];
        __syncwarp();
        for (int r = 0; r < n; r++) {
            int start = r & 1;
            for (int i = start + 2 * lane; i + 1 < n; i += 64) {
                int x = buf[wd][i], y = buf[wd][i + 1];
                if (x > y) { buf[wd][i] = y; buf[wd][i + 1] = x; }
            }
            __syncwarp();
        }
        for (int i = lane; i < n; i += 32) g_pairlist[s + i] = buf[wd][i];
    } else if (lane == 0) {
        for (int i = s + 1; i < e; i++) {
            int v = g_pairlist[i];
            int j = i - 1;
            while (j >= s && g_pairlist[j] > v) { g_pairlist[j + 1] = g_pairlist[j]; j--; }
            g_pairlist[j + 1] = v;
        }
    }
}

// ---------------- K4: hot kernel — ix + per-atom segment sum --------------
// PERSISTENT warps + atomic work queue: kills wave quantization and
// block-granularity load imbalance. Per-atom body identical to R5
// (2-pair pipelined, scalar FFMA, __stcs streaming stores).
__device__ __forceinline__ void pair_body(
        int p, int j, int lane,
        const float* __restrict__ px, const float* __restrict__ i1,
        const float* __restrict__ diff, float* __restrict__ ix,
        float4& a0, float4& a1, float4& a2) {
    float4 sv = __ldcs((const float4*)(i1 + (size_t)p * NPROP) + lane);
    float d0 = __ldg(&diff[3 * p + 0]);
    float d1 = __ldg(&diff[3 * p + 1]);
    float d2 = __ldg(&diff[3 * p + 2]);
    const float4* pxj = (const float4*)(px + (size_t)j * 3 * NPROP);
    float4 p0 = __ldg(pxj + lane);
    float4 p1 = __ldg(pxj + 32 + lane);
    float4 p2 = __ldg(pxj + 64 + lane);

    float4 v0, v1, v2;
    v0.x = fmaf(p0.x, sv.x, d0 * sv.x); v0.y = fmaf(p0.y, sv.y, d0 * sv.y);
    v0.z = fmaf(p0.z, sv.z, d0 * sv.z); v0.w = fmaf(p0.w, sv.w, d0 * sv.w);
    v1.x = fmaf(p1.x, sv.x, d1 * sv.x); v1.y = fmaf(p1.y, sv.y, d1 * sv.y);
    v1.z = fmaf(p1.z, sv.z, d1 * sv.z); v1.w = fmaf(p1.w, sv.w, d1 * sv.w);
    v2.x = fmaf(p2.x, sv.x, d2 * sv.x); v2.y = fmaf(p2.y, sv.y, d2 * sv.y);
    v2.z = fmaf(p2.z, sv.z, d2 * sv.z); v2.w = fmaf(p2.w, sv.w, d2 * sv.w);

    float4* op = (float4*)(ix + (size_t)p * 3 * NPROP);
    __stcs(op + lane,      v0);
    __stcs(op + 32 + lane, v1);
    __stcs(op + 64 + lane, v2);

    a0.x += v0.x; a0.y += v0.y; a0.z += v0.z; a0.w += v0.w;
    a1.x += v1.x; a1.y += v1.y; a1.z += v1.z; a1.w += v1.w;
    a2.x += v2.x; a2.y += v2.y; a2.z += v2.z; a2.w += v2.w;
}

__global__ void __launch_bounds__(128) k_accum(
        const int*   __restrict__ ind2,
        const float* __restrict__ px,
        const float* __restrict__ i1,
        const float* __restrict__ diff,
        float*       __restrict__ ix) {
    int lane = threadIdx.x & 31;

    while (true) {
        int a;
        if (lane == 0) a = atomicAdd(&g_next, 1);
        a = __shfl_sync(0xffffffff, a, 0);
        if (a >= N_ATOMS) break;

        int s = g_offsets[a], e = g_offsets[a + 1];

        float4 a0 = make_float4(0.f, 0.f, 0.f, 0.f);
        float4 a1 = a0, a2 = a0;

        int pA = 0, jA = 0, pB = 0, jB = 0;
        if (s < e)     { pA = g_pairlist[s];     jA = __ldg(&ind2[2 * pA + 1]); }
        if (s + 1 < e) { pB = g_pairlist[s + 1]; jB = __ldg(&ind2[2 * pB + 1]); }

        int k = s;
        for (; k + 1 < e; k += 2) {
            int pa = pA, ja = jA, pb = pB, jb = jB;
            if (k + 2 < e) { pA = g_pairlist[k + 2]; jA = __ldg(&ind2[2 * pA + 1]); }
            if (k + 3 < e) { pB = g_pairlist[k + 3]; jB = __ldg(&ind2[2 * pB + 1]); }
            pair_body(pa, ja, lane, px, i1, diff, ix, a0, a1, a2);
            pair_body(pb, jb, lane, px, i1, diff, ix, a0, a1, a2);
        }
        if (k < e) {
            pair_body(pA, jA, lane, px, i1, diff, ix, a0, a1, a2);
        }

        float4* ap = (float4*)(g_pxacc + (size_t)a * 3 * NPROP);
        ap[lane]      = a0;
        ap[32 + lane] = a1;
        ap[64 + lane] = a2;
    }
}

// ---------------- K5: px_new = acc @ w_pp, dotted = sum_x px_new^2 --------
// (R2/R4 version.) q-split: grid.y selects a 64-wide half of q; 40KB shared.
__global__ void __launch_bounds__(128) k_gemm(
        const float* __restrict__ w,
        float*       __restrict__ pxnew,
        float*       __restrict__ dotted) {
    __shared__ float  sw[128 * 64];           // 32KB: w[:, qh*64 .. qh*64+63]
    __shared__ float4 sacc[4][NPROP];         // 8KB

    int tid = threadIdx.x, wd = tid >> 5, lane = tid & 31;
    int qh = blockIdx.y;

    for (int i = tid; i < 2048; i += 128) {
        int c = i >> 4, f4 = i & 15;
        ((float4*)sw)[i] = __ldg((const float4*)(w + (size_t)c * NPROP + qh * 64) + f4);
    }
    __syncthreads();

    int abase = blockIdx.x * 32 + wd * 8;
    for (int t = 0; t < 8; t++) {
        int a = abase + t;
        if (a >= N_ATOMS) break;
        const float* ap = g_pxacc + (size_t)a * 3 * NPROP;
#pragma unroll
        for (int r = 0; r < 4; r++) {
            int c = lane + 32 * r;
            sacc[wd][c] = make_float4(ap[c], ap[NPROP + c], ap[2 * NPROP + c], 0.f);
        }
        __syncwarp();

        float2 o0 = make_float2(0.f, 0.f), o1 = o0, o2 = o0;
#pragma unroll 8
        for (int c = 0; c < NPROP; c++) {
            float2 wv = ((const float2*)sw)[c * 32 + lane];
            float4 av = sacc[wd][c];
            o0.x = fmaf(av.x, wv.x, o0.x); o0.y = fmaf(av.x, wv.y, o0.y);
            o1.x = fmaf(av.y, wv.x, o1.x); o1.y = fmaf(av.y, wv.y, o1.y);
            o2.x = fmaf(av.z, wv.x, o2.x); o2.y = fmaf(av.z, wv.y, o2.y);
        }

        float* pn = pxnew + (size_t)a * 3 * NPROP + qh * 64;
        ((float2*)pn)[lane]                = o0;
        ((float2*)(pn + NPROP))[lane]      = o1;
        ((float2*)(pn + 2 * NPROP))[lane]  = o2;

        float2 dv;
        dv.x = o0.x * o0.x + o1.x * o1.x + o2.x * o2.x;
        dv.y = o0.y * o0.y + o1.y * o1.y + o2.y * o2.y;
        ((float2*)(dotted + (size_t)a * NPROP + qh * 64))[lane] = dv;
        __syncwarp();
    }
}

// ---------------- launch ----------------
extern "C" void kernel_launch(void* const* d_in, const int* in_sizes, int n_in,
                              void* d_out, int out_size) {
    const int*   ind2 = (const int*)  d_in[0];
    const float* px   = (const float*)d_in[1];
    const float* i1   = (const float*)d_in[2];
    const float* diff = (const float*)d_in[3];
    const float* w    = (const float*)d_in[4];

    float* out   = (float*)d_out;
    float* pxnew = out;                                  // 10000*3*128
    float* ixo   = out + 3840000LL;                      // 250000*3*128
    float* dot   = out + 99840000LL;                     // 10000*128

    k_init   <<<(N_ATOMS + 255) / 256, 256>>>();
    k_hist   <<<(N_PAIRS + 255) / 256, 256>>>(ind2);
    k_scan   <<<1, 1024>>>();
    k_scatter<<<(N_PAIRS + 255) / 256, 256>>>(ind2);
    k_sort   <<<(N_ATOMS + 3) / 4, 128>>>();
    k_accum  <<<1184, 128>>>(ind2, px, i1, diff, ixo);   // persistent, 1 wave

    dim3 gg((N_ATOMS + 31) / 32, 2);
    k_gemm   <<<gg, 128>>>(w, pxnew, dot);
}

// round 7
// speedup vs baseline: 1.0027x; 1.0027x over previous
#include <cuda_runtime.h>
#include <cuda_bf16.h>
#include <cstdint>

#define N_ATOMS 10000
#define N_PAIRS 250000
#define NPROP   128

// ---------------- device scratch (static, allocation-free) ----------------
// Zero-initialized at module load; k_scan re-zeroes counts/cursor each call
// so every graph replay sees the same initial state.
__device__ int   g_counts[N_ATOMS];
__device__ int   g_cursor[N_ATOMS];
__device__ int   g_offsets[N_ATOMS + 1];
__device__ int   g_pairlist[N_PAIRS];
__device__ float g_pxacc[(size_t)N_ATOMS * 3 * NPROP];

// ---------------- K1: histogram of ind_i ----------------
__global__ void k_hist(const int* __restrict__ ind2) {
    int p = blockIdx.x * blockDim.x + threadIdx.x;
    if (p < N_PAIRS) atomicAdd(&g_counts[ind2[2 * p]], 1);
}

// ---------------- K2: exclusive scan + self-cleaning (1 block) ------------
__global__ void k_scan() {
    __shared__ int part[1024];
    const int PER = 10;
    int t = threadIdx.x;
    int local[PER];
    int sum = 0;
#pragma unroll
    for (int r = 0; r < PER; r++) {
        int idx = t * PER + r;
        int v = 0;
        if (idx < N_ATOMS) {
            v = g_counts[idx];
            g_counts[idx] = 0;                // re-zero for next replay
            g_cursor[idx] = 0;                // reset scatter cursor
        }
        local[r] = sum;
        sum += v;
    }
    part[t] = sum;
    __syncthreads();
    for (int off = 1; off < 1024; off <<= 1) {
        int v = (t >= off) ? part[t - off] : 0;
        __syncthreads();
        part[t] += v;
        __syncthreads();
    }
    int base = (t > 0) ? part[t - 1] : 0;
#pragma unroll
    for (int r = 0; r < PER; r++) {
        int idx = t * PER + r;
        if (idx < N_ATOMS) g_offsets[idx] = base + local[r];
    }
    if (t == 1023) g_offsets[N_ATOMS] = part[1023];
}

// ---------------- K3: scatter pair ids into CSR ----------------
__global__ void k_scatter(const int* __restrict__ ind2) {
    int p = blockIdx.x * blockDim.x + threadIdx.x;
    if (p < N_PAIRS) {
        int i = ind2[2 * p];
        int pos = atomicAdd(&g_cursor[i], 1);
        g_pairlist[g_offsets[i] + pos] = p;
    }
}

// ---------------- K4: hot kernel — sort + ix + per-atom segment sum -------
// One warp per atom. Segment pair-ids staged into shared, odd-even sorted
// there (deterministic sum order), then consumed directly from shared.
// Value path identical to R5: 2-pair pipelined, scalar FFMA, __stcs stores.
__device__ __forceinline__ void pair_body(
        int p, int j, int lane,
        const float* __restrict__ px, const float* __restrict__ i1,
        const float* __restrict__ diff, float* __restrict__ ix,
        float4& a0, float4& a1, float4& a2) {
    float4 sv = __ldcs((const float4*)(i1 + (size_t)p * NPROP) + lane);
    float d0 = __ldg(&diff[3 * p + 0]);
    float d1 = __ldg(&diff[3 * p + 1]);
    float d2 = __ldg(&diff[3 * p + 2]);
    const float4* pxj = (const float4*)(px + (size_t)j * 3 * NPROP);
    float4 p0 = __ldg(pxj + lane);
    float4 p1 = __ldg(pxj + 32 + lane);
    float4 p2 = __ldg(pxj + 64 + lane);

    float4 v0, v1, v2;
    v0.x = fmaf(p0.x, sv.x, d0 * sv.x); v0.y = fmaf(p0.y, sv.y, d0 * sv.y);
    v0.z = fmaf(p0.z, sv.z, d0 * sv.z); v0.w = fmaf(p0.w, sv.w, d0 * sv.w);
    v1.x = fmaf(p1.x, sv.x, d1 * sv.x); v1.y = fmaf(p1.y, sv.y, d1 * sv.y);
    v1.z = fmaf(p1.z, sv.z, d1 * sv.z); v1.w = fmaf(p1.w, sv.w, d1 * sv.w);
    v2.x = fmaf(p2.x, sv.x, d2 * sv.x); v2.y = fmaf(p2.y, sv.y, d2 * sv.y);
    v2.z = fmaf(p2.z, sv.z, d2 * sv.z); v2.w = fmaf(p2.w, sv.w, d2 * sv.w);

    float4* op = (float4*)(ix + (size_t)p * 3 * NPROP);
    __stcs(op + lane,      v0);
    __stcs(op + 32 + lane, v1);
    __stcs(op + 64 + lane, v2);

    a0.x += v0.x; a0.y += v0.y; a0.z += v0.z; a0.w += v0.w;
    a1.x += v1.x; a1.y += v1.y; a1.z += v1.z; a1.w += v1.w;
    a2.x += v2.x; a2.y += v2.y; a2.z += v2.z; a2.w += v2.w;
}

__global__ void __launch_bounds__(128) k_accum(
        const int*   __restrict__ ind2,
        const float* __restrict__ px,
        const float* __restrict__ i1,
        const float* __restrict__ diff,
        float*       __restrict__ ix) {
    __shared__ int buf[4][96];
    int wd   = threadIdx.x >> 5;
    int lane = threadIdx.x & 31;
    int a = blockIdx.x * 4 + wd;              // grid = N_ATOMS/4 exactly
    int s = g_offsets[a], e = g_offsets[a + 1];
    int n = e - s;

    // stage + sort segment in shared (deterministic order)
    const int* plist;
    if (n <= 96) {
        for (int i = lane; i < n; i += 32) buf[wd][i] = g_pairlist[s + i];
        __syncwarp();
        for (int r = 0; r < n; r++) {
            int start = r & 1;
            for (int i = start + 2 * lane; i + 1 < n; i += 64) {
                int x = buf[wd][i], y = buf[wd][i + 1];
                if (x > y) { buf[wd][i] = y; buf[wd][i + 1] = x; }
            }
            __syncwarp();
        }
        plist = buf[wd];
    } else {
        if (lane == 0) {                       // overflow fallback (P~0)
            for (int i = s + 1; i < e; i++) {
                int v = g_pairlist[i];
                int j = i - 1;
                while (j >= s && g_pairlist[j] > v) { g_pairlist[j + 1] = g_pairlist[j]; j--; }
                g_pairlist[j + 1] = v;
            }
        }
        __syncwarp();
        plist = &g_pairlist[s];
    }

    float4 a0 = make_float4(0.f, 0.f, 0.f, 0.f);
    float4 a1 = a0, a2 = a0;

    int pA = 0, jA = 0, pB = 0, jB = 0;
    if (n > 0) { pA = plist[0]; jA = __ldg(&ind2[2 * pA + 1]); }
    if (n > 1) { pB = plist[1]; jB = __ldg(&ind2[2 * pB + 1]); }

    int k = 0;
    for (; k + 1 < n; k += 2) {
        int pa = pA, ja = jA, pb = pB, jb = jB;
        if (k + 2 < n) { pA = plist[k + 2]; jA = __ldg(&ind2[2 * pA + 1]); }
        if (k + 3 < n) { pB = plist[k + 3]; jB = __ldg(&ind2[2 * pB + 1]); }
        pair_body(pa, ja, lane, px, i1, diff, ix, a0, a1, a2);
        pair_body(pb, jb, lane, px, i1, diff, ix, a0, a1, a2);
    }
    if (k < n) {
        pair_body(pA, jA, lane, px, i1, diff, ix, a0, a1, a2);
    }

    float4* ap = (float4*)(g_pxacc + (size_t)a * 3 * NPROP);
    ap[lane]      = a0;
    ap[32 + lane] = a1;
    ap[64 + lane] = a2;
}

// ---------------- K5: px_new = acc @ w_pp, dotted = sum_x px_new^2 --------
__global__ void __launch_bounds__(128) k_gemm(
        const float* __restrict__ w,
        float*       __restrict__ pxnew,
        float*       __restrict__ dotted) {
    __shared__ float  sw[128 * 64];           // 32KB: w[:, qh*64 .. qh*64+63]
    __shared__ float4 sacc[4][NPROP];         // 8KB

    int tid = threadIdx.x, wd = tid >> 5, lane = tid & 31;
    int qh = blockIdx.y;

    for (int i = tid; i < 2048; i += 128) {
        int c = i >> 4, f4 = i & 15;
        ((float4*)sw)[i] = __ldg((const float4*)(w + (size_t)c * NPROP + qh * 64) + f4);
    }
    __syncthreads();

    int abase = blockIdx.x * 32 + wd * 8;
    for (int t = 0; t < 8; t++) {
        int a = abase + t;
        if (a >= N_ATOMS) break;
        const float* ap = g_pxacc + (size_t)a * 3 * NPROP;
#pragma unroll
        for (int r = 0; r < 4; r++) {
            int c = lane + 32 * r;
            sacc[wd][c] = make_float4(ap[c], ap[NPROP + c], ap[2 * NPROP + c], 0.f);
        }
        __syncwarp();

        float2 o0 = make_float2(0.f, 0.f), o1 = o0, o2 = o0;
#pragma unroll 8
        for (int c = 0; c < NPROP; c++) {
            float2 wv = ((const float2*)sw)[c * 32 + lane];
            float4 av = sacc[wd][c];
            o0.x = fmaf(av.x, wv.x, o0.x); o0.y = fmaf(av.x, wv.y, o0.y);
            o1.x = fmaf(av.y, wv.x, o1.x); o1.y = fmaf(av.y, wv.y, o1.y);
            o2.x = fmaf(av.z, wv.x, o2.x); o2.y = fmaf(av.z, wv.y, o2.y);
        }

        float* pn = pxnew + (size_t)a * 3 * NPROP + qh * 64;
        ((float2*)pn)[lane]                = o0;
        ((float2*)(pn + NPROP))[lane]      = o1;
        ((float2*)(pn + 2 * NPROP))[lane]  = o2;

        float2 dv;
        dv.x = o0.x * o0.x + o1.x * o1.x + o2.x * o2.x;
        dv.y = o0.y * o0.y + o1.y * o1.y + o2.y * o2.y;
        ((float2*)(dotted + (size_t)a * NPROP + qh * 64))[lane] = dv;
        __syncwarp();
    }
}

// ---------------- launch (5 kernels; k_accum is overall launch #6 -> ncu) -
extern "C" void kernel_launch(void* const* d_in, const int* in_sizes, int n_in,
                              void* d_out, int out_size) {
    const int*   ind2 = (const int*)  d_in[0];
    const float* px   = (const float*)d_in[1];
    const float* i1   = (const float*)d_in[2];
    const float* diff = (const float*)d_in[3];
    const float* w    = (const float*)d_in[4];

    float* out   = (float*)d_out;
    float* pxnew = out;                                  // 10000*3*128
    float* ixo   = out + 3840000LL;                      // 250000*3*128
    float* dot   = out + 99840000LL;                     // 10000*128

    k_hist   <<<(N_PAIRS + 255) / 256, 256>>>(ind2);
    k_scan   <<<1, 1024>>>();
    k_scatter<<<(N_PAIRS + 255) / 256, 256>>>(ind2);
    k_accum  <<<N_ATOMS / 4, 128>>>(ind2, px, i1, diff, ixo);

    dim3 gg((N_ATOMS + 31) / 32, 2);
    k_gemm   <<<gg, 128>>>(w, pxnew, dot);
}